// round 12
// baseline (speedup 1.0000x reference)
#include <cuda_runtime.h>
#include <cuda_bf16.h>
#include <cstdint>

#define NN 50000
#define NE 500000
#define DD 256
#define KW 512

// ---------------- static device scratch ----------------
__device__ __align__(16) float g_xa[(size_t)NN * DD];   // x @ W1a + b1
__device__ __align__(16) float g_agg[(size_t)NN * DD];  // scatter-sum
__device__ float g_cnt[NN];                             // counts -> 1/max(cnt,1)
// weights transposed to [w][n][k] bf16, hi and lo parts (w: 0=W1, 1=W2)
__device__ __align__(16) unsigned short g_wh[2u * 256u * KW];
__device__ __align__(16) unsigned short g_wl[2u * 256u * KW];

// ---------------- helpers ----------------
static __device__ __forceinline__ uint32_t smem_u32(const void* p) {
    uint32_t a;
    asm("{ .reg .u64 t; cvta.to.shared.u64 t, %1; cvt.u32.u64 %0, t; }" : "=r"(a) : "l"(p));
    return a;
}
static __device__ __forceinline__ uint32_t pack2(__nv_bfloat16 a, __nv_bfloat16 b) {
    return (uint32_t)__bfloat16_as_ushort(a) | ((uint32_t)__bfloat16_as_ushort(b) << 16);
}

#define LDSM4(r0, r1, r2, r3, addr)                                          \
    asm volatile("ldmatrix.sync.aligned.m8n8.x4.shared.b16 {%0,%1,%2,%3}, [%4];" \
                 : "=r"(r0), "=r"(r1), "=r"(r2), "=r"(r3) : "r"(addr))

#define MMA16816(d, a, b0, b1)                                               \
    asm volatile("mma.sync.aligned.m16n8k16.row.col.f32.bf16.bf16.f32 "      \
                 "{%0,%1,%2,%3},{%4,%5,%6,%7},{%8,%9},{%0,%1,%2,%3};"        \
                 : "+f"((d)[0]), "+f"((d)[1]), "+f"((d)[2]), "+f"((d)[3])    \
                 : "r"((a)[0]), "r"((a)[1]), "r"((a)[2]), "r"((a)[3]),       \
                   "r"(b0), "r"(b1))

// ---------------- tiny kernels ----------------
__global__ void zero_kernel() {
    int stride = gridDim.x * blockDim.x;
    int tid = blockIdx.x * blockDim.x + threadIdx.x;
    for (int i = tid; i < NN * DD; i += stride) g_agg[i] = 0.0f;
    for (int i = tid; i < NN; i += stride) g_cnt[i] = 0.0f;
}
__global__ void rinv_kernel() {
    int i = blockIdx.x * blockDim.x + threadIdx.x;
    if (i < NN) g_cnt[i] = 1.0f / fmaxf(g_cnt[i], 1.0f);
}
// transpose W[k][n] f32 -> [n][k] bf16 hi/lo
__global__ void prep_kernel(const float* __restrict__ W1, const float* __restrict__ W2) {
    int t = blockIdx.x * blockDim.x + threadIdx.x;
    if (t >= 2 * 64 * 256) return;
    int n = t & 255;
    int k0 = ((t >> 8) & 63) * 8;
    int w = t >> 14;
    const float* W = w ? W2 : W1;
#pragma unroll
    for (int i = 0; i < 8; i++) {
        int k = k0 + i;
        float v = W[(size_t)k * DD + n];
        __nv_bfloat16 h = __float2bfloat16(v);
        float r = v - __bfloat162float(h);
        size_t o = ((size_t)w * 256 + n) * KW + k;
        g_wh[o] = __bfloat16_as_ushort(h);
        g_wl[o] = __bfloat16_as_ushort(__float2bfloat16(r));
    }
}

// ---------------- HMMA GEMM ----------------
// CTA tile 128(M) x 128(N); gridDim.x = 2 N-halves (fast-varying, L2 A-reuse)
// Double-buffered smem stages; fragment reuse across the 3 bf16 splits.
// MODE 0: g_xa = x @ W1a + b1                                 (M=NN, K=256)
// MODE 1: h = relu(ea @ W1b + g_xa[row]); red into g_agg[col] (M=NE, K=256)
// MODE 2: out = relu(x @ W2a + (agg*rinv) @ W2b + b2)         (M=NN, K=512)
template <int MODE>
__global__ __launch_bounds__(256, 2)
void gemm_kernel(const float* __restrict__ x, const float* __restrict__ ea,
                 const int* __restrict__ eidx, const float* __restrict__ bias,
                 float* __restrict__ outp)
{
    // [stage][plane(hi/lo)][128 rows x 16 k bf16, swizzled]
    __shared__ __align__(16) unsigned char sA[2][2][4096];
    __shared__ __align__(16) unsigned char sB[2][2][4096];
    __shared__ int rs[128], cs[128];
    __shared__ float srv[128];

    const int tid = threadIdx.x, lane = tid & 31, wid = tid >> 5;
    const int wm = wid >> 1, wn = wid & 1;   // warp grid 4(M) x 2(N), warp tile 32x64
    const int n0 = blockIdx.x * 128;         // N-half
    const int m0 = blockIdx.y * 128;

    if (MODE == 1 && tid < 128) {
        int e = min(m0 + tid, NE - 1);
        rs[tid] = eidx[e];
        cs[tid] = eidx[NE + e];
    }
    if (MODE == 2 && tid < 128) {
        int m = m0 + tid;
        srv[tid] = (m < NN) ? g_cnt[m] : 0.0f;
    }

    uint32_t sAb[2][2], sBb[2][2];
#pragma unroll
    for (int s = 0; s < 2; s++)
#pragma unroll
        for (int p = 0; p < 2; p++) {
            sAb[s][p] = smem_u32(sA[s][p]);
            sBb[s][p] = smem_u32(sB[s][p]);
        }

    float4 aST[2];
    uint4  bST[2];

    auto loadRegs = [&](int ks) {
        // A: 128 rows x 16 k f32 -> 512 float4, 2 per thread
#pragma unroll
        for (int j = 0; j < 2; j++) {
            int idx = tid + j * 256;
            int row = idx >> 2, kk = idx & 3;
            if (MODE == 1) {
                int gm = min(m0 + row, NE - 1);
                aST[j] = *(const float4*)&ea[(size_t)gm * DD + ks * 16 + kk * 4];
            } else if (MODE == 0) {
                int gm = min(m0 + row, NN - 1);
                aST[j] = *(const float4*)&x[(size_t)gm * DD + ks * 16 + kk * 4];
            } else {
                int gm = min(m0 + row, NN - 1);
                if (ks < 16) {
                    aST[j] = *(const float4*)&x[(size_t)gm * DD + ks * 16 + kk * 4];
                } else {
                    float4 v = *(const float4*)&g_agg[(size_t)gm * DD + (ks - 16) * 16 + kk * 4];
                    float s = srv[row];
                    v.x *= s; v.y *= s; v.z *= s; v.w *= s;
                    aST[j] = v;
                }
            }
        }
        // B: 128 n-rows x 16 k bf16, hi+lo: one uint4 per plane per thread
        const int w  = (MODE == 2) ? 1 : 0;
        const int kb = (MODE == 1) ? 256 + ks * 16 : ks * 16;
        {
            int n = tid >> 1, c = tid & 1;
            size_t o = ((size_t)w * 256 + n0 + n) * KW + kb + c * 8;
            bST[0] = *(const uint4*)&g_wh[o];
            bST[1] = *(const uint4*)&g_wl[o];
        }
    };
    auto storeStage = [&](int buf) {
#pragma unroll
        for (int j = 0; j < 2; j++) {
            int idx = tid + j * 256;
            int row = idx >> 2, kk = idx & 3;
            int c = kk >> 1;
            uint32_t off = row * 32 + (((c ^ ((row >> 2) & 1)) << 4)) + (kk & 1) * 8;
            float4 v = aST[j];
            __nv_bfloat16 h0 = __float2bfloat16(v.x), h1 = __float2bfloat16(v.y);
            __nv_bfloat16 h2 = __float2bfloat16(v.z), h3 = __float2bfloat16(v.w);
            __nv_bfloat16 l0 = __float2bfloat16(v.x - __bfloat162float(h0));
            __nv_bfloat16 l1 = __float2bfloat16(v.y - __bfloat162float(h1));
            __nv_bfloat16 l2 = __float2bfloat16(v.z - __bfloat162float(h2));
            __nv_bfloat16 l3 = __float2bfloat16(v.w - __bfloat162float(h3));
            *(uint2*)(sA[buf][0] + off) = make_uint2(pack2(h0, h1), pack2(h2, h3));
            *(uint2*)(sA[buf][1] + off) = make_uint2(pack2(l0, l1), pack2(l2, l3));
        }
        {
            int n = tid >> 1, c = tid & 1;
            uint32_t off = n * 32 + ((c ^ ((n >> 2) & 1)) << 4);
            *(uint4*)(sB[buf][0] + off) = bST[0];
            *(uint4*)(sB[buf][1] + off) = bST[1];
        }
    };

    float acc[2][8][4];
#pragma unroll
    for (int a = 0; a < 2; a++)
#pragma unroll
        for (int b = 0; b < 8; b++)
#pragma unroll
            for (int q = 0; q < 4; q++) acc[a][b][q] = 0.0f;

    auto compute = [&](int buf) {
        // Load A frags ONCE (hi+lo), reuse across splits: 4 LDSM4
        uint32_t afrH[2][4], afrL[2][4];
#pragma unroll
        for (int mi = 0; mi < 2; mi++) {
            int row = wm * 32 + mi * 16 + (lane & 7) + ((lane >> 3) & 1) * 8;
            int c = lane >> 4;
            uint32_t off = row * 32 + ((c ^ ((row >> 2) & 1)) << 4);
            LDSM4(afrH[mi][0], afrH[mi][1], afrH[mi][2], afrH[mi][3], sAb[buf][0] + off);
            LDSM4(afrL[mi][0], afrL[mi][1], afrL[mi][2], afrL[mi][3], sAb[buf][1] + off);
        }
#pragma unroll
        for (int np = 0; np < 4; np++) {
            int n = wn * 64 + np * 16 + (lane & 7) + ((lane >> 4) & 1) * 8;
            int c = (lane >> 3) & 1;
            uint32_t off = n * 32 + ((c ^ ((n >> 2) & 1)) << 4);
            uint32_t bH[4], bL[4];
            LDSM4(bH[0], bH[1], bH[2], bH[3], sBb[buf][0] + off);
            LDSM4(bL[0], bL[1], bL[2], bL[3], sBb[buf][1] + off);
#pragma unroll
            for (int mi = 0; mi < 2; mi++) {
                MMA16816(acc[mi][np * 2 + 0], afrH[mi], bH[0], bH[1]);
                MMA16816(acc[mi][np * 2 + 1], afrH[mi], bH[2], bH[3]);
                MMA16816(acc[mi][np * 2 + 0], afrH[mi], bL[0], bL[1]);
                MMA16816(acc[mi][np * 2 + 1], afrH[mi], bL[2], bL[3]);
                MMA16816(acc[mi][np * 2 + 0], afrL[mi], bH[0], bH[1]);
                MMA16816(acc[mi][np * 2 + 1], afrL[mi], bH[2], bH[3]);
            }
        }
    };

    const int NK = (MODE == 2) ? 32 : 16;
    int buf = 0;
    loadRegs(0);
    for (int ks = 0; ks < NK; ks++) {
        storeStage(buf);
        __syncthreads();     // stage[buf] visible; also releases stage[buf^1] for next store
        if (ks + 1 < NK) loadRegs(ks + 1);
        compute(buf);
        buf ^= 1;
    }

    // ---------------- epilogue ----------------
    const int colb = n0 + wn * 64 + (lane & 3) * 2;
    if (MODE == 1) {
#pragma unroll
        for (int mi = 0; mi < 2; mi++) {
#pragma unroll
            for (int h = 0; h < 2; h++) {
                int lr = wm * 32 + mi * 16 + (lane >> 2) + h * 8;
                bool valid = (m0 + lr < NE);
                if (!valid) continue;
                int srcr = rs[lr], dstc = cs[lr];
                const float* xr = &g_xa[(size_t)srcr * DD];
                float* ag = &g_agg[(size_t)dstc * DD];
#pragma unroll
                for (int nt = 0; nt < 8; nt++) {
                    int n = colb + nt * 8;
                    float2 xv = *(const float2*)&xr[n];
                    float v0 = fmaxf(acc[mi][nt][h * 2 + 0] + xv.x, 0.0f);
                    float v1 = fmaxf(acc[mi][nt][h * 2 + 1] + xv.y, 0.0f);
                    asm volatile("red.global.add.v2.f32 [%0], {%1,%2};"
                                 :: "l"(ag + n), "f"(v0), "f"(v1) : "memory");
                }
            }
        }
        if (blockIdx.x == 0 && tid < 128 && m0 + tid < NE)
            atomicAdd(&g_cnt[cs[tid]], 1.0f);
    } else {
#pragma unroll
        for (int mi = 0; mi < 2; mi++) {
#pragma unroll
            for (int h = 0; h < 2; h++) {
                int row = m0 + wm * 32 + mi * 16 + (lane >> 2) + h * 8;
                if (row >= NN) continue;
                float* dst = (MODE == 0) ? &g_xa[(size_t)row * DD] : &outp[(size_t)row * DD];
#pragma unroll
                for (int nt = 0; nt < 8; nt++) {
                    int n = colb + nt * 8;
                    float2 bb = *(const float2*)&bias[n];
                    float2 v;
                    v.x = acc[mi][nt][h * 2 + 0] + bb.x;
                    v.y = acc[mi][nt][h * 2 + 1] + bb.y;
                    if (MODE == 2) { v.x = fmaxf(v.x, 0.0f); v.y = fmaxf(v.y, 0.0f); }
                    *(float2*)&dst[n] = v;
                }
            }
        }
    }
}

// ---------------------------------------------------------------------------
extern "C" void kernel_launch(void* const* d_in, const int* in_sizes, int n_in,
                              void* d_out, int out_size) {
    const float* x  = (const float*)d_in[0];
    const int* eix  = (const int*)d_in[1];   // int32 (jax x64 disabled)
    const float* ea = (const float*)d_in[2];
    const float* W1 = (const float*)d_in[5];
    const float* b1 = (const float*)d_in[6];
    const float* W2 = (const float*)d_in[7];
    const float* b2 = (const float*)d_in[8];
    float* out      = (float*)d_out;
    (void)in_sizes; (void)n_in; (void)out_size;

    zero_kernel<<<2048, 256>>>();
    prep_kernel<<<128, 256>>>(W1, W2);
    dim3 gN(2, (NN + 127) / 128);
    dim3 gE(2, (NE + 127) / 128);
    gemm_kernel<0><<<gN, 256>>>(x, ea, eix, b1, nullptr);
    gemm_kernel<1><<<gE, 256>>>(x, ea, eix, b1, nullptr);
    rinv_kernel<<<(NN + 255) / 256, 256>>>();
    gemm_kernel<2><<<gN, 256>>>(x, ea, eix, b2, out);
}